// round 8
// baseline (speedup 1.0000x reference)
#include <cuda_runtime.h>
#include <cuda_bf16.h>
#include <cstdint>

// Problem constants: B=4, L=2048, D_MODEL=1024, H=16, Dh=Dv=64
#define BB 4
#define LL 2048
#define DM 1024
#define HH 16
#define DH 64
#define MROWS (BB * LL)   // 8192

__device__ float g_Q[MROWS * DM];
__device__ float g_K[MROWS * DM];
__device__ float g_V[MROWS * DM];
__device__ float g_ctx[MROWS * DM];

// ---------------------------------------------------------------------------
// helpers
// ---------------------------------------------------------------------------
__device__ __forceinline__ unsigned f2tf(float f) {
    unsigned u;
    asm("cvt.rna.tf32.f32 %0, %1;" : "=r"(u) : "f"(f));
    return u;
}
__device__ __forceinline__ unsigned scvta(const void* p) {
    return (unsigned)__cvta_generic_to_shared(p);
}
__device__ __forceinline__ void ldsm4(unsigned& r0, unsigned& r1, unsigned& r2,
                                      unsigned& r3, unsigned a) {
    asm volatile("ldmatrix.sync.aligned.m8n8.x4.shared.b16 {%0,%1,%2,%3},[%4];"
                 : "=r"(r0), "=r"(r1), "=r"(r2), "=r"(r3) : "r"(a));
}
__device__ __forceinline__ void mma8(float* c, unsigned a0, unsigned a1,
                                     unsigned a2, unsigned a3, unsigned b0,
                                     unsigned b1) {
    asm volatile(
        "mma.sync.aligned.m16n8k8.row.col.f32.tf32.tf32.f32 "
        "{%0,%1,%2,%3},{%4,%5,%6,%7},{%8,%9},{%0,%1,%2,%3};"
        : "+f"(c[0]), "+f"(c[1]), "+f"(c[2]), "+f"(c[3])
        : "r"(a0), "r"(a1), "r"(a2), "r"(a3), "r"(b0), "r"(b1));
}
__device__ __forceinline__ float fexp(float x) {
    float y = fmaxf(x * 1.4426950408889634f, -126.0f);
    float z = y + 12582912.0f;
    int   e = __float_as_int(z) << 23;
    float f = y - (z - 12582912.0f);
    float p = fmaf(1.33336e-3f, f, 9.61813e-3f);
    p = fmaf(p, f, 5.55041e-2f);
    p = fmaf(p, f, 0.240227f);
    p = fmaf(p, f, 0.693147f);
    p = fmaf(p, f, 1.0f);
    return __int_as_float(__float_as_int(p) + e);
}

// ---------------------------------------------------------------------------
// tf32 SGEMM v3: double-buffered smem, one barrier per chunk.
// Tile 256x128, BK=32, 8 warps, warp tile 64x64.
// smem word(row,col) = row*32 + ((col/4 ^ (row&7))*4) + col%4
// buffers: As[2] (8192 words each), Bs[2] (4096 words each) = 96KB
// ---------------------------------------------------------------------------
#define GEMM_SMEM 98304

__device__ __forceinline__ void gemm_body(const float* __restrict__ A,
                                          const float* __restrict__ W,
                                          float* __restrict__ C) {
    extern __shared__ unsigned gsm[];
    // layout: As0 @0, As1 @8192, Bs0 @16384, Bs1 @20480 (words)

    const int tid = threadIdx.x, lane = tid & 31, warp = tid >> 5;
    const int wm = warp & 3, wn = warp >> 2;
    const int row0 = blockIdx.y * 256, col0 = blockIdx.x * 128;
    const int lsub = lane >> 3, lr = lane & 7;
    const int g = lane >> 2, tg = lane & 3;
    const unsigned sbase = scvta(gsm);

    int ar[8], aq[8], asw[8];
#pragma unroll
    for (int p = 0; p < 8; ++p) {
        const int i = p * 256 + tid;
        ar[p] = i >> 3; aq[p] = i & 7;
        asw[p] = (ar[p] << 5) + ((aq[p] ^ (ar[p] & 7)) << 2);
    }
    int br[4], bq[4], bsw[4];
#pragma unroll
    for (int p = 0; p < 4; ++p) {
        const int i = p * 256 + tid;
        br[p] = i >> 3; bq[p] = i & 7;
        bsw[p] = (br[p] << 5) + ((bq[p] ^ (br[p] & 7)) << 2);
    }

    float acc[4][8][4] = {};
    float4 av[8], bv[4];

    // prologue: chunk 0 -> regs -> buf0
#pragma unroll
    for (int p = 0; p < 8; ++p)
        av[p] = *(const float4*)(A + (size_t)(row0 + ar[p]) * DM + aq[p] * 4);
#pragma unroll
    for (int p = 0; p < 4; ++p)
        bv[p] = *(const float4*)(W + (size_t)(col0 + br[p]) * DM + bq[p] * 4);
#pragma unroll
    for (int p = 0; p < 8; ++p) {
        uint4 u;
        u.x = f2tf(av[p].x); u.y = f2tf(av[p].y);
        u.z = f2tf(av[p].z); u.w = f2tf(av[p].w);
        *(uint4*)(gsm + asw[p]) = u;
    }
#pragma unroll
    for (int p = 0; p < 4; ++p) {
        uint4 u;
        u.x = f2tf(bv[p].x); u.y = f2tf(bv[p].y);
        u.z = f2tf(bv[p].z); u.w = f2tf(bv[p].w);
        *(uint4*)(gsm + 16384 + bsw[p]) = u;
    }
    __syncthreads();

    for (int c = 0; c < 32; ++c) {
        const int cur = c & 1, nxt = cur ^ 1;
        const bool more = c < 31;
        // prefetch next chunk into regs (hidden under mma below)
        if (more) {
            const int kk = (c + 1) * 32;
#pragma unroll
            for (int p = 0; p < 8; ++p)
                av[p] = *(const float4*)(A + (size_t)(row0 + ar[p]) * DM + kk + aq[p] * 4);
#pragma unroll
            for (int p = 0; p < 4; ++p)
                bv[p] = *(const float4*)(W + (size_t)(col0 + br[p]) * DM + kk + bq[p] * 4);
        }

        const unsigned asb = sbase + cur * 32768u;
        const unsigned bsb = sbase + 65536u + cur * 16384u;
#pragma unroll
        for (int ks = 0; ks < 4; ++ks) {
            const int ch = ks * 2;
            unsigned a[4][4], b[4][4];
#pragma unroll
            for (int mf = 0; mf < 4; ++mf) {
                const int r = wm * 64 + mf * 16 + ((lsub & 1) << 3) + lr;
                const unsigned ad =
                    asb + (((r << 5) + (((ch + (lsub >> 1)) ^ (r & 7)) << 2)) << 2);
                ldsm4(a[mf][0], a[mf][1], a[mf][2], a[mf][3], ad);
            }
#pragma unroll
            for (int np = 0; np < 4; ++np) {
                const int r = wn * 64 + np * 16 + ((lsub >> 1) << 3) + lr;
                const unsigned bd =
                    bsb + (((r << 5) + (((ch + (lsub & 1)) ^ (r & 7)) << 2)) << 2);
                ldsm4(b[np][0], b[np][1], b[np][2], b[np][3], bd);
            }
#pragma unroll
            for (int mf = 0; mf < 4; ++mf)
#pragma unroll
                for (int np = 0; np < 4; ++np) {
                    mma8(acc[mf][np * 2 + 0], a[mf][0], a[mf][1], a[mf][2], a[mf][3],
                         b[np][0], b[np][1]);
                    mma8(acc[mf][np * 2 + 1], a[mf][0], a[mf][1], a[mf][2], a[mf][3],
                         b[np][2], b[np][3]);
                }
        }

        // store next chunk into the other buffer (overlaps tail of mma)
        if (more) {
            unsigned* Asn = gsm + nxt * 8192;
            unsigned* Bsn = gsm + 16384 + nxt * 4096;
#pragma unroll
            for (int p = 0; p < 8; ++p) {
                uint4 u;
                u.x = f2tf(av[p].x); u.y = f2tf(av[p].y);
                u.z = f2tf(av[p].z); u.w = f2tf(av[p].w);
                *(uint4*)(Asn + asw[p]) = u;
            }
#pragma unroll
            for (int p = 0; p < 4; ++p) {
                uint4 u;
                u.x = f2tf(bv[p].x); u.y = f2tf(bv[p].y);
                u.z = f2tf(bv[p].z); u.w = f2tf(bv[p].w);
                *(uint4*)(Bsn + bsw[p]) = u;
            }
        }
        __syncthreads();
    }

#pragma unroll
    for (int mf = 0; mf < 4; ++mf)
#pragma unroll
        for (int nf = 0; nf < 8; ++nf) {
            const int row = row0 + wm * 64 + mf * 16 + g;
            const int col = col0 + wn * 64 + nf * 8 + 2 * tg;
            *(float2*)(C + (size_t)row * DM + col) =
                make_float2(acc[mf][nf][0], acc[mf][nf][1]);
            *(float2*)(C + (size_t)(row + 8) * DM + col) =
                make_float2(acc[mf][nf][2], acc[mf][nf][3]);
        }
}

__global__ void __launch_bounds__(256, 1)
qkv_gemm(const float* __restrict__ x, const float* __restrict__ Wq,
         const float* __restrict__ Wk, const float* __restrict__ Wv) {
    const float* W = (blockIdx.z == 0) ? Wq : (blockIdx.z == 1) ? Wk : Wv;
    float* C = (blockIdx.z == 0) ? g_Q : (blockIdx.z == 1) ? g_K : g_V;
    gemm_body(x, W, C);
}

__global__ void __launch_bounds__(256, 1)
out_gemm(const float* __restrict__ Wo, float* __restrict__ out) {
    gemm_body(g_ctx, Wo, out);
}

// ---------------------------------------------------------------------------
// Flash attention v3: 256 threads (8 warps), Br=256, Bc=64, 32 q-rows/warp.
// K and Vt double-buffered -> ONE __syncthreads per kv-tile; stores for t+1
// issue right after QK(t). smem 192KB, 1 CTA/SM (2 warps/SMSP unchanged).
// word(row,col) = row*64 + ((col/4 ^ (row&7))*4) + col%4
// layout (words): Qs @0 (16384), Ps @16384 (16384), K0 @32768, K1 @36864,
//                 V0 @40960, V1 @45056, madd2 @49152 (2x64 floats)
// ---------------------------------------------------------------------------
#define ATT_SMEM (49152 * 4 + 2 * 64 * 4)

__global__ void __launch_bounds__(256, 1)
flash_tf32(const unsigned char* __restrict__ mask) {
    extern __shared__ unsigned sm[];
    unsigned* Qs = sm;
    unsigned* Ps = sm + 16384;
    float* madd2 = (float*)(sm + 49152);

    const int tid = threadIdx.x, lane = tid & 31, warp = tid >> 5;
    const int lsub = lane >> 3, lr = lane & 7;
    const int g = lane >> 2, tg = lane & 3;
    const int bh = blockIdx.y, b = bh >> 4, h = bh & 15;
    const int q0 = blockIdx.x * 256;
    const size_t hoff = (size_t)b * LL * DM + (size_t)h * DH;
    const unsigned qsb = scvta(Qs), psb = scvta(Ps);
    const unsigned kb0 = scvta(sm + 32768), vb0 = scvta(sm + 40960);

    // K/V load geometry: K 4 float4/thread, V 4 float4/thread
    const int vkey = tid & 63, vquar = tid >> 6;   // quarter owns d 16*q..16*q+15

    float4 kv_k[4], kv_v[4];
    unsigned char mv = 0;

    // prologue: Q tile (scaled) -> smem
#pragma unroll
    for (int p = 0; p < 16; ++p) {
        const int idx = p * 256 + tid;
        const int r = idx >> 4, q = idx & 15;
        const float4 v = *(const float4*)(g_Q + hoff + (size_t)(q0 + r) * DM + q * 4);
        const int w = (r << 6) + ((q ^ (r & 7)) << 2);
        Qs[w + 0] = f2tf(v.x * 0.125f); Qs[w + 1] = f2tf(v.y * 0.125f);
        Qs[w + 2] = f2tf(v.z * 0.125f); Qs[w + 3] = f2tf(v.w * 0.125f);
    }
    // first K/V tile -> regs -> buf0
#pragma unroll
    for (int p = 0; p < 4; ++p) {
        const int idx = p * 256 + tid;
        const int r = idx >> 4, q = idx & 15;
        kv_k[p] = *(const float4*)(g_K + hoff + (size_t)r * DM + q * 4);
    }
#pragma unroll
    for (int dq = 0; dq < 4; ++dq) {
        const int d = vquar * 16 + dq * 4;
        kv_v[dq] = *(const float4*)(g_V + hoff + (size_t)vkey * DM + d);
    }
    if (tid < 64) mv = mask[(size_t)b * LL + tid];
    {
        unsigned* K0 = sm + 32768;
        unsigned* V0 = sm + 40960;
#pragma unroll
        for (int p = 0; p < 4; ++p) {
            const int idx = p * 256 + tid;
            const int r = idx >> 4, q = idx & 15;
            const int w = (r << 6) + ((q ^ (r & 7)) << 2);
            K0[w + 0] = f2tf(kv_k[p].x); K0[w + 1] = f2tf(kv_k[p].y);
            K0[w + 2] = f2tf(kv_k[p].z); K0[w + 3] = f2tf(kv_k[p].w);
        }
#pragma unroll
        for (int dq = 0; dq < 4; ++dq) {
            const int d = vquar * 16 + dq * 4;
            const float4 v = kv_v[dq];
            V0[(d + 0) * 64 + ((((vkey >> 2) ^ ((d + 0) & 7))) << 2) + (vkey & 3)] = f2tf(v.x);
            V0[(d + 1) * 64 + ((((vkey >> 2) ^ ((d + 1) & 7))) << 2) + (vkey & 3)] = f2tf(v.y);
            V0[(d + 2) * 64 + ((((vkey >> 2) ^ ((d + 2) & 7))) << 2) + (vkey & 3)] = f2tf(v.z);
            V0[(d + 3) * 64 + ((((vkey >> 2) ^ ((d + 3) & 7))) << 2) + (vkey & 3)] = f2tf(v.w);
        }
        if (tid < 64) madd2[tid] = mv ? -1e30f : 0.0f;
    }
    __syncthreads();

    float m[2][2], l[2][2];
#pragma unroll
    for (int mf = 0; mf < 2; ++mf) { m[mf][0] = m[mf][1] = -1e30f; l[mf][0] = l[mf][1] = 0.0f; }
    float o[2][8][4] = {};

    for (int t = 0; t < 32; ++t) {
        const int cur = t & 1, nxt = cur ^ 1;
        const bool more = t < 31;
        const int kv0 = t * 64;
        const unsigned ksb = kb0 + cur * 16384u;
        const unsigned vtb = vb0 + cur * 16384u;
        const float* maddc = madd2 + cur * 64;

        // prefetch next K/V/mask into regs
        if (more) {
#pragma unroll
            for (int p = 0; p < 4; ++p) {
                const int idx = p * 256 + tid;
                const int r = idx >> 4, q = idx & 15;
                kv_k[p] = *(const float4*)(g_K + hoff + (size_t)(kv0 + 64 + r) * DM + q * 4);
            }
#pragma unroll
            for (int dq = 0; dq < 4; ++dq) {
                const int d = vquar * 16 + dq * 4;
                kv_v[dq] = *(const float4*)(g_V + hoff + (size_t)(kv0 + 64 + vkey) * DM + d);
            }
            if (tid < 64) mv = mask[(size_t)b * LL + kv0 + 64 + tid];
        }

        // S = (Q*0.125) K^T
        float s[2][8][4] = {};
#pragma unroll
        for (int ks = 0; ks < 8; ++ks) {
            const int ch = ks * 2;
            unsigned a[2][4];
#pragma unroll
            for (int mf = 0; mf < 2; ++mf) {
                const int r = warp * 32 + mf * 16 + ((lsub & 1) << 3) + lr;
                const unsigned ad =
                    qsb + (((r << 6) + (((ch + (lsub >> 1)) ^ (r & 7)) << 2)) << 2);
                ldsm4(a[mf][0], a[mf][1], a[mf][2], a[mf][3], ad);
            }
#pragma unroll
            for (int np = 0; np < 4; ++np) {
                const int r = np * 16 + ((lsub >> 1) << 3) + lr;
                const unsigned bd =
                    ksb + (((r << 6) + (((ch + (lsub & 1)) ^ (r & 7)) << 2)) << 2);
                unsigned b0, b1, b2, b3;
                ldsm4(b0, b1, b2, b3, bd);
#pragma unroll
                for (int mf = 0; mf < 2; ++mf) {
                    mma8(s[mf][np * 2 + 0], a[mf][0], a[mf][1], a[mf][2], a[mf][3], b0, b1);
                    mma8(s[mf][np * 2 + 1], a[mf][0], a[mf][1], a[mf][2], a[mf][3], b2, b3);
                }
            }
        }

        // store next K/V/mask into other buffer (safe: t-1 readers done at last sync)
        if (more) {
            unsigned* Kn = sm + 32768 + nxt * 4096;
            unsigned* Vn = sm + 40960 + nxt * 4096;
#pragma unroll
            for (int p = 0; p < 4; ++p) {
                const int idx = p * 256 + tid;
                const int r = idx >> 4, q = idx & 15;
                const int w = (r << 6) + ((q ^ (r & 7)) << 2);
                Kn[w + 0] = f2tf(kv_k[p].x); Kn[w + 1] = f2tf(kv_k[p].y);
                Kn[w + 2] = f2tf(kv_k[p].z); Kn[w + 3] = f2tf(kv_k[p].w);
            }
#pragma unroll
            for (int dq = 0; dq < 4; ++dq) {
                const int d = vquar * 16 + dq * 4;
                const float4 v = kv_v[dq];
                Vn[(d + 0) * 64 + ((((vkey >> 2) ^ ((d + 0) & 7))) << 2) + (vkey & 3)] = f2tf(v.x);
                Vn[(d + 1) * 64 + ((((vkey >> 2) ^ ((d + 1) & 7))) << 2) + (vkey & 3)] = f2tf(v.y);
                Vn[(d + 2) * 64 + ((((vkey >> 2) ^ ((d + 2) & 7))) << 2) + (vkey & 3)] = f2tf(v.z);
                Vn[(d + 3) * 64 + ((((vkey >> 2) ^ ((d + 3) & 7))) << 2) + (vkey & 3)] = f2tf(v.w);
            }
            if (tid < 64) madd2[nxt * 64 + tid] = mv ? -1e30f : 0.0f;
        }

        // mask + online softmax
#pragma unroll
        for (int mf = 0; mf < 2; ++mf) {
            float rm0 = -1e30f, rm1 = -1e30f;
#pragma unroll
            for (int nf = 0; nf < 8; ++nf) {
                const float2 ma = *(const float2*)&maddc[nf * 8 + 2 * tg];
                s[mf][nf][0] += ma.x; s[mf][nf][1] += ma.y;
                s[mf][nf][2] += ma.x; s[mf][nf][3] += ma.y;
                rm0 = fmaxf(rm0, fmaxf(s[mf][nf][0], s[mf][nf][1]));
                rm1 = fmaxf(rm1, fmaxf(s[mf][nf][2], s[mf][nf][3]));
            }
            rm0 = fmaxf(rm0, __shfl_xor_sync(0xffffffffu, rm0, 1));
            rm0 = fmaxf(rm0, __shfl_xor_sync(0xffffffffu, rm0, 2));
            rm1 = fmaxf(rm1, __shfl_xor_sync(0xffffffffu, rm1, 1));
            rm1 = fmaxf(rm1, __shfl_xor_sync(0xffffffffu, rm1, 2));
            const float mn0 = fmaxf(m[mf][0], rm0), mn1 = fmaxf(m[mf][1], rm1);
            const float corr0 = fexp(m[mf][0] - mn0), corr1 = fexp(m[mf][1] - mn1);
            m[mf][0] = mn0; m[mf][1] = mn1;

            float rs0 = 0.0f, rs1 = 0.0f;
            const int prow0 = warp * 32 + mf * 16 + g;
#pragma unroll
            for (int nf = 0; nf < 8; ++nf) {
                const float p0 = fexp(s[mf][nf][0] - mn0);
                const float p1 = fexp(s[mf][nf][1] - mn0);
                const float p2 = fexp(s[mf][nf][2] - mn1);
                const float p3 = fexp(s[mf][nf][3] - mn1);
                rs0 += p0 + p1; rs1 += p2 + p3;
                const int col = nf * 8 + 2 * tg;
                const int w0 = (prow0 << 6) + ((((col >> 2) ^ (prow0 & 7))) << 2) + (col & 3);
                *(uint2*)&Ps[w0] = make_uint2(f2tf(p0), f2tf(p1));
                const int prow1 = prow0 + 8;
                const int w1 = (prow1 << 6) + ((((col >> 2) ^ (prow1 & 7))) << 2) + (col & 3);
                *(uint2*)&Ps[w1] = make_uint2(f2tf(p2), f2tf(p3));
            }
            rs0 += __shfl_xor_sync(0xffffffffu, rs0, 1);
            rs0 += __shfl_xor_sync(0xffffffffu, rs0, 2);
            rs1 += __shfl_xor_sync(0xffffffffu, rs1, 1);
            rs1 += __shfl_xor_sync(0xffffffffu, rs1, 2);
            l[mf][0] = l[mf][0] * corr0 + rs0;
            l[mf][1] = l[mf][1] * corr1 + rs1;
#pragma unroll
            for (int nf = 0; nf < 8; ++nf) {
                o[mf][nf][0] *= corr0; o[mf][nf][1] *= corr0;
                o[mf][nf][2] *= corr1; o[mf][nf][3] *= corr1;
            }
        }
        __syncwarp();

        // O += P V
#pragma unroll
        for (int ks = 0; ks < 8; ++ks) {
            const int ch = ks * 2;
            unsigned a[2][4];
#pragma unroll
            for (int mf = 0; mf < 2; ++mf) {
                const int r = warp * 32 + mf * 16 + ((lsub & 1) << 3) + lr;
                const unsigned ad =
                    psb + (((r << 6) + (((ch + (lsub >> 1)) ^ (r & 7)) << 2)) << 2);
                ldsm4(a[mf][0], a[mf][1], a[mf][2], a[mf][3], ad);
            }
#pragma unroll
            for (int np = 0; np < 4; ++np) {
                const int rv = np * 16 + ((lsub >> 1) << 3) + lr;
                const unsigned bd =
                    vtb + (((rv << 6) + (((ch + (lsub & 1)) ^ (rv & 7)) << 2)) << 2);
                unsigned b0, b1, b2, b3;
                ldsm4(b0, b1, b2, b3, bd);
#pragma unroll
                for (int mf = 0; mf < 2; ++mf) {
                    mma8(o[mf][np * 2 + 0], a[mf][0], a[mf][1], a[mf][2], a[mf][3], b0, b1);
                    mma8(o[mf][np * 2 + 1], a[mf][0], a[mf][1], a[mf][2], a[mf][3], b2, b3);
                }
            }
        }
        __syncthreads();   // single barrier per tile
    }

    // epilogue -> g_ctx (B, L, H*Dv)
#pragma unroll
    for (int mf = 0; mf < 2; ++mf) {
        const float inv0 = 1.0f / l[mf][0], inv1 = 1.0f / l[mf][1];
#pragma unroll
        for (int nf = 0; nf < 8; ++nf) {
            const int row = q0 + warp * 32 + mf * 16 + g;
            const int col = nf * 8 + 2 * tg;
            *(float2*)(g_ctx + hoff + (size_t)row * DM + col) =
                make_float2(o[mf][nf][0] * inv0, o[mf][nf][1] * inv0);
            *(float2*)(g_ctx + hoff + (size_t)(row + 8) * DM + col) =
                make_float2(o[mf][nf][2] * inv1, o[mf][nf][3] * inv1);
        }
    }
}

// ---------------------------------------------------------------------------
// Launch
// ---------------------------------------------------------------------------
extern "C" void kernel_launch(void* const* d_in, const int* in_sizes, int n_in,
                              void* d_out, int out_size) {
    const float* x          = (const float*)d_in[0];
    const unsigned char* mk = (const unsigned char*)d_in[1];
    const float* Wq         = (const float*)d_in[2];
    const float* Wk         = (const float*)d_in[3];
    const float* Wv         = (const float*)d_in[4];
    const float* Wo         = (const float*)d_in[5];
    float* out              = (float*)d_out;

    cudaFuncSetAttribute(qkv_gemm, cudaFuncAttributeMaxDynamicSharedMemorySize,
                         GEMM_SMEM);
    cudaFuncSetAttribute(out_gemm, cudaFuncAttributeMaxDynamicSharedMemorySize,
                         GEMM_SMEM);
    cudaFuncSetAttribute(flash_tf32, cudaFuncAttributeMaxDynamicSharedMemorySize,
                         ATT_SMEM);

    dim3 gq(DM / 128, MROWS / 256, 3);   // (8, 32, 3)
    qkv_gemm<<<gq, 256, GEMM_SMEM>>>(x, Wq, Wk, Wv);

    dim3 gf(LL / 256, BB * HH);          // (8, 64)
    flash_tf32<<<gf, 256, ATT_SMEM>>>(mk);

    dim3 go(DM / 128, MROWS / 256, 1);   // (8, 32)
    out_gemm<<<go, 256, GEMM_SMEM>>>(Wo, out);
}

// round 9
// speedup vs baseline: 1.0004x; 1.0004x over previous
#include <cuda_runtime.h>
#include <cuda_bf16.h>
#include <cstdint>

// Problem constants: B=4, L=2048, D_MODEL=1024, H=16, Dh=Dv=64
#define BB 4
#define LL 2048
#define DM 1024
#define HH 16
#define DH 64
#define MROWS (BB * LL)   // 8192

__device__ float g_Q[MROWS * DM];
__device__ float g_K[MROWS * DM];
__device__ float g_V[MROWS * DM];
__device__ float g_ctx[MROWS * DM];

// ---------------------------------------------------------------------------
// helpers
// ---------------------------------------------------------------------------
__device__ __forceinline__ unsigned f2tf(float f) {
    unsigned u;
    asm("cvt.rna.tf32.f32 %0, %1;" : "=r"(u) : "f"(f));
    return u;
}
__device__ __forceinline__ unsigned scvta(const void* p) {
    return (unsigned)__cvta_generic_to_shared(p);
}
__device__ __forceinline__ void ldsm4(unsigned& r0, unsigned& r1, unsigned& r2,
                                      unsigned& r3, unsigned a) {
    asm volatile("ldmatrix.sync.aligned.m8n8.x4.shared.b16 {%0,%1,%2,%3},[%4];"
                 : "=r"(r0), "=r"(r1), "=r"(r2), "=r"(r3) : "r"(a));
}
__device__ __forceinline__ void mma8(float* c, unsigned a0, unsigned a1,
                                     unsigned a2, unsigned a3, unsigned b0,
                                     unsigned b1) {
    asm volatile(
        "mma.sync.aligned.m16n8k8.row.col.f32.tf32.tf32.f32 "
        "{%0,%1,%2,%3},{%4,%5,%6,%7},{%8,%9},{%0,%1,%2,%3};"
        : "+f"(c[0]), "+f"(c[1]), "+f"(c[2]), "+f"(c[3])
        : "r"(a0), "r"(a1), "r"(a2), "r"(a3), "r"(b0), "r"(b1));
}
__device__ __forceinline__ float fexp(float x) {
    float y = fmaxf(x * 1.4426950408889634f, -126.0f);
    float z = y + 12582912.0f;
    int   e = __float_as_int(z) << 23;
    float f = y - (z - 12582912.0f);
    float p = fmaf(1.33336e-3f, f, 9.61813e-3f);
    p = fmaf(p, f, 5.55041e-2f);
    p = fmaf(p, f, 0.240227f);
    p = fmaf(p, f, 0.693147f);
    p = fmaf(p, f, 1.0f);
    return __int_as_float(__float_as_int(p) + e);
}

// ---------------------------------------------------------------------------
// tf32 SGEMM v3: double-buffered smem, one barrier per chunk.
// Tile 256x128, BK=32, 8 warps, warp tile 64x64.
// smem word(row,col) = row*32 + ((col/4 ^ (row&7))*4) + col%4
// buffers: As[2] (8192 words each), Bs[2] (4096 words each) = 96KB
// ---------------------------------------------------------------------------
#define GEMM_SMEM 98304

__device__ __forceinline__ void gemm_body(const float* __restrict__ A,
                                          const float* __restrict__ W,
                                          float* __restrict__ C) {
    extern __shared__ unsigned gsm[];
    // layout: As0 @0, As1 @8192, Bs0 @16384, Bs1 @20480 (words)

    const int tid = threadIdx.x, lane = tid & 31, warp = tid >> 5;
    const int wm = warp & 3, wn = warp >> 2;
    const int row0 = blockIdx.y * 256, col0 = blockIdx.x * 128;
    const int lsub = lane >> 3, lr = lane & 7;
    const int g = lane >> 2, tg = lane & 3;
    const unsigned sbase = scvta(gsm);

    int ar[8], aq[8], asw[8];
#pragma unroll
    for (int p = 0; p < 8; ++p) {
        const int i = p * 256 + tid;
        ar[p] = i >> 3; aq[p] = i & 7;
        asw[p] = (ar[p] << 5) + ((aq[p] ^ (ar[p] & 7)) << 2);
    }
    int br[4], bq[4], bsw[4];
#pragma unroll
    for (int p = 0; p < 4; ++p) {
        const int i = p * 256 + tid;
        br[p] = i >> 3; bq[p] = i & 7;
        bsw[p] = (br[p] << 5) + ((bq[p] ^ (br[p] & 7)) << 2);
    }

    float acc[4][8][4] = {};
    float4 av[8], bv[4];

    // prologue: chunk 0 -> regs -> buf0
#pragma unroll
    for (int p = 0; p < 8; ++p)
        av[p] = *(const float4*)(A + (size_t)(row0 + ar[p]) * DM + aq[p] * 4);
#pragma unroll
    for (int p = 0; p < 4; ++p)
        bv[p] = *(const float4*)(W + (size_t)(col0 + br[p]) * DM + bq[p] * 4);
#pragma unroll
    for (int p = 0; p < 8; ++p) {
        uint4 u;
        u.x = f2tf(av[p].x); u.y = f2tf(av[p].y);
        u.z = f2tf(av[p].z); u.w = f2tf(av[p].w);
        *(uint4*)(gsm + asw[p]) = u;
    }
#pragma unroll
    for (int p = 0; p < 4; ++p) {
        uint4 u;
        u.x = f2tf(bv[p].x); u.y = f2tf(bv[p].y);
        u.z = f2tf(bv[p].z); u.w = f2tf(bv[p].w);
        *(uint4*)(gsm + 16384 + bsw[p]) = u;
    }
    __syncthreads();

    for (int c = 0; c < 32; ++c) {
        const int cur = c & 1, nxt = cur ^ 1;
        const bool more = c < 31;
        // prefetch next chunk into regs (hidden under mma below)
        if (more) {
            const int kk = (c + 1) * 32;
#pragma unroll
            for (int p = 0; p < 8; ++p)
                av[p] = *(const float4*)(A + (size_t)(row0 + ar[p]) * DM + kk + aq[p] * 4);
#pragma unroll
            for (int p = 0; p < 4; ++p)
                bv[p] = *(const float4*)(W + (size_t)(col0 + br[p]) * DM + kk + bq[p] * 4);
        }

        const unsigned asb = sbase + cur * 32768u;
        const unsigned bsb = sbase + 65536u + cur * 16384u;
#pragma unroll
        for (int ks = 0; ks < 4; ++ks) {
            const int ch = ks * 2;
            unsigned a[4][4], b[4][4];
#pragma unroll
            for (int mf = 0; mf < 4; ++mf) {
                const int r = wm * 64 + mf * 16 + ((lsub & 1) << 3) + lr;
                const unsigned ad =
                    asb + (((r << 5) + (((ch + (lsub >> 1)) ^ (r & 7)) << 2)) << 2);
                ldsm4(a[mf][0], a[mf][1], a[mf][2], a[mf][3], ad);
            }
#pragma unroll
            for (int np = 0; np < 4; ++np) {
                const int r = wn * 64 + np * 16 + ((lsub >> 1) << 3) + lr;
                const unsigned bd =
                    bsb + (((r << 5) + (((ch + (lsub & 1)) ^ (r & 7)) << 2)) << 2);
                ldsm4(b[np][0], b[np][1], b[np][2], b[np][3], bd);
            }
#pragma unroll
            for (int mf = 0; mf < 4; ++mf)
#pragma unroll
                for (int np = 0; np < 4; ++np) {
                    mma8(acc[mf][np * 2 + 0], a[mf][0], a[mf][1], a[mf][2], a[mf][3],
                         b[np][0], b[np][1]);
                    mma8(acc[mf][np * 2 + 1], a[mf][0], a[mf][1], a[mf][2], a[mf][3],
                         b[np][2], b[np][3]);
                }
        }

        // store next chunk into the other buffer (overlaps tail of mma)
        if (more) {
            unsigned* Asn = gsm + nxt * 8192;
            unsigned* Bsn = gsm + 16384 + nxt * 4096;
#pragma unroll
            for (int p = 0; p < 8; ++p) {
                uint4 u;
                u.x = f2tf(av[p].x); u.y = f2tf(av[p].y);
                u.z = f2tf(av[p].z); u.w = f2tf(av[p].w);
                *(uint4*)(Asn + asw[p]) = u;
            }
#pragma unroll
            for (int p = 0; p < 4; ++p) {
                uint4 u;
                u.x = f2tf(bv[p].x); u.y = f2tf(bv[p].y);
                u.z = f2tf(bv[p].z); u.w = f2tf(bv[p].w);
                *(uint4*)(Bsn + bsw[p]) = u;
            }
        }
        __syncthreads();
    }

#pragma unroll
    for (int mf = 0; mf < 4; ++mf)
#pragma unroll
        for (int nf = 0; nf < 8; ++nf) {
            const int row = row0 + wm * 64 + mf * 16 + g;
            const int col = col0 + wn * 64 + nf * 8 + 2 * tg;
            *(float2*)(C + (size_t)row * DM + col) =
                make_float2(acc[mf][nf][0], acc[mf][nf][1]);
            *(float2*)(C + (size_t)(row + 8) * DM + col) =
                make_float2(acc[mf][nf][2], acc[mf][nf][3]);
        }
}

__global__ void __launch_bounds__(256, 1)
qkv_gemm(const float* __restrict__ x, const float* __restrict__ Wq,
         const float* __restrict__ Wk, const float* __restrict__ Wv) {
    const float* W = (blockIdx.z == 0) ? Wq : (blockIdx.z == 1) ? Wk : Wv;
    float* C = (blockIdx.z == 0) ? g_Q : (blockIdx.z == 1) ? g_K : g_V;
    gemm_body(x, W, C);
}

__global__ void __launch_bounds__(256, 1)
out_gemm(const float* __restrict__ Wo, float* __restrict__ out) {
    gemm_body(g_ctx, Wo, out);
}

// ---------------------------------------------------------------------------
// Flash attention v3: 256 threads (8 warps), Br=256, Bc=64, 32 q-rows/warp.
// K and Vt double-buffered -> ONE __syncthreads per kv-tile; stores for t+1
// issue right after QK(t). smem 192KB, 1 CTA/SM (2 warps/SMSP unchanged).
// word(row,col) = row*64 + ((col/4 ^ (row&7))*4) + col%4
// layout (words): Qs @0 (16384), Ps @16384 (16384), K0 @32768, K1 @36864,
//                 V0 @40960, V1 @45056, madd2 @49152 (2x64 floats)
// ---------------------------------------------------------------------------
#define ATT_SMEM (49152 * 4 + 2 * 64 * 4)

__global__ void __launch_bounds__(256, 1)
flash_tf32(const unsigned char* __restrict__ mask) {
    extern __shared__ unsigned sm[];
    unsigned* Qs = sm;
    unsigned* Ps = sm + 16384;
    float* madd2 = (float*)(sm + 49152);

    const int tid = threadIdx.x, lane = tid & 31, warp = tid >> 5;
    const int lsub = lane >> 3, lr = lane & 7;
    const int g = lane >> 2, tg = lane & 3;
    const int bh = blockIdx.y, b = bh >> 4, h = bh & 15;
    const int q0 = blockIdx.x * 256;
    const size_t hoff = (size_t)b * LL * DM + (size_t)h * DH;
    const unsigned qsb = scvta(Qs), psb = scvta(Ps);
    const unsigned kb0 = scvta(sm + 32768), vb0 = scvta(sm + 40960);

    // K/V load geometry: K 4 float4/thread, V 4 float4/thread
    const int vkey = tid & 63, vquar = tid >> 6;   // quarter owns d 16*q..16*q+15

    float4 kv_k[4], kv_v[4];
    unsigned char mv = 0;

    // prologue: Q tile (scaled) -> smem
#pragma unroll
    for (int p = 0; p < 16; ++p) {
        const int idx = p * 256 + tid;
        const int r = idx >> 4, q = idx & 15;
        const float4 v = *(const float4*)(g_Q + hoff + (size_t)(q0 + r) * DM + q * 4);
        const int w = (r << 6) + ((q ^ (r & 7)) << 2);
        Qs[w + 0] = f2tf(v.x * 0.125f); Qs[w + 1] = f2tf(v.y * 0.125f);
        Qs[w + 2] = f2tf(v.z * 0.125f); Qs[w + 3] = f2tf(v.w * 0.125f);
    }
    // first K/V tile -> regs -> buf0
#pragma unroll
    for (int p = 0; p < 4; ++p) {
        const int idx = p * 256 + tid;
        const int r = idx >> 4, q = idx & 15;
        kv_k[p] = *(const float4*)(g_K + hoff + (size_t)r * DM + q * 4);
    }
#pragma unroll
    for (int dq = 0; dq < 4; ++dq) {
        const int d = vquar * 16 + dq * 4;
        kv_v[dq] = *(const float4*)(g_V + hoff + (size_t)vkey * DM + d);
    }
    if (tid < 64) mv = mask[(size_t)b * LL + tid];
    {
        unsigned* K0 = sm + 32768;
        unsigned* V0 = sm + 40960;
#pragma unroll
        for (int p = 0; p < 4; ++p) {
            const int idx = p * 256 + tid;
            const int r = idx >> 4, q = idx & 15;
            const int w = (r << 6) + ((q ^ (r & 7)) << 2);
            K0[w + 0] = f2tf(kv_k[p].x); K0[w + 1] = f2tf(kv_k[p].y);
            K0[w + 2] = f2tf(kv_k[p].z); K0[w + 3] = f2tf(kv_k[p].w);
        }
#pragma unroll
        for (int dq = 0; dq < 4; ++dq) {
            const int d = vquar * 16 + dq * 4;
            const float4 v = kv_v[dq];
            V0[(d + 0) * 64 + ((((vkey >> 2) ^ ((d + 0) & 7))) << 2) + (vkey & 3)] = f2tf(v.x);
            V0[(d + 1) * 64 + ((((vkey >> 2) ^ ((d + 1) & 7))) << 2) + (vkey & 3)] = f2tf(v.y);
            V0[(d + 2) * 64 + ((((vkey >> 2) ^ ((d + 2) & 7))) << 2) + (vkey & 3)] = f2tf(v.z);
            V0[(d + 3) * 64 + ((((vkey >> 2) ^ ((d + 3) & 7))) << 2) + (vkey & 3)] = f2tf(v.w);
        }
        if (tid < 64) madd2[tid] = mv ? -1e30f : 0.0f;
    }
    __syncthreads();

    float m[2][2], l[2][2];
#pragma unroll
    for (int mf = 0; mf < 2; ++mf) { m[mf][0] = m[mf][1] = -1e30f; l[mf][0] = l[mf][1] = 0.0f; }
    float o[2][8][4] = {};

    for (int t = 0; t < 32; ++t) {
        const int cur = t & 1, nxt = cur ^ 1;
        const bool more = t < 31;
        const int kv0 = t * 64;
        const unsigned ksb = kb0 + cur * 16384u;
        const unsigned vtb = vb0 + cur * 16384u;
        const float* maddc = madd2 + cur * 64;

        // prefetch next K/V/mask into regs
        if (more) {
#pragma unroll
            for (int p = 0; p < 4; ++p) {
                const int idx = p * 256 + tid;
                const int r = idx >> 4, q = idx & 15;
                kv_k[p] = *(const float4*)(g_K + hoff + (size_t)(kv0 + 64 + r) * DM + q * 4);
            }
#pragma unroll
            for (int dq = 0; dq < 4; ++dq) {
                const int d = vquar * 16 + dq * 4;
                kv_v[dq] = *(const float4*)(g_V + hoff + (size_t)(kv0 + 64 + vkey) * DM + d);
            }
            if (tid < 64) mv = mask[(size_t)b * LL + kv0 + 64 + tid];
        }

        // S = (Q*0.125) K^T
        float s[2][8][4] = {};
#pragma unroll
        for (int ks = 0; ks < 8; ++ks) {
            const int ch = ks * 2;
            unsigned a[2][4];
#pragma unroll
            for (int mf = 0; mf < 2; ++mf) {
                const int r = warp * 32 + mf * 16 + ((lsub & 1) << 3) + lr;
                const unsigned ad =
                    qsb + (((r << 6) + (((ch + (lsub >> 1)) ^ (r & 7)) << 2)) << 2);
                ldsm4(a[mf][0], a[mf][1], a[mf][2], a[mf][3], ad);
            }
#pragma unroll
            for (int np = 0; np < 4; ++np) {
                const int r = np * 16 + ((lsub >> 1) << 3) + lr;
                const unsigned bd =
                    ksb + (((r << 6) + (((ch + (lsub & 1)) ^ (r & 7)) << 2)) << 2);
                unsigned b0, b1, b2, b3;
                ldsm4(b0, b1, b2, b3, bd);
#pragma unroll
                for (int mf = 0; mf < 2; ++mf) {
                    mma8(s[mf][np * 2 + 0], a[mf][0], a[mf][1], a[mf][2], a[mf][3], b0, b1);
                    mma8(s[mf][np * 2 + 1], a[mf][0], a[mf][1], a[mf][2], a[mf][3], b2, b3);
                }
            }
        }

        // store next K/V/mask into other buffer (safe: t-1 readers done at last sync)
        if (more) {
            unsigned* Kn = sm + 32768 + nxt * 4096;
            unsigned* Vn = sm + 40960 + nxt * 4096;
#pragma unroll
            for (int p = 0; p < 4; ++p) {
                const int idx = p * 256 + tid;
                const int r = idx >> 4, q = idx & 15;
                const int w = (r << 6) + ((q ^ (r & 7)) << 2);
                Kn[w + 0] = f2tf(kv_k[p].x); Kn[w + 1] = f2tf(kv_k[p].y);
                Kn[w + 2] = f2tf(kv_k[p].z); Kn[w + 3] = f2tf(kv_k[p].w);
            }
#pragma unroll
            for (int dq = 0; dq < 4; ++dq) {
                const int d = vquar * 16 + dq * 4;
                const float4 v = kv_v[dq];
                Vn[(d + 0) * 64 + ((((vkey >> 2) ^ ((d + 0) & 7))) << 2) + (vkey & 3)] = f2tf(v.x);
                Vn[(d + 1) * 64 + ((((vkey >> 2) ^ ((d + 1) & 7))) << 2) + (vkey & 3)] = f2tf(v.y);
                Vn[(d + 2) * 64 + ((((vkey >> 2) ^ ((d + 2) & 7))) << 2) + (vkey & 3)] = f2tf(v.z);
                Vn[(d + 3) * 64 + ((((vkey >> 2) ^ ((d + 3) & 7))) << 2) + (vkey & 3)] = f2tf(v.w);
            }
            if (tid < 64) madd2[nxt * 64 + tid] = mv ? -1e30f : 0.0f;
        }

        // mask + online softmax
#pragma unroll
        for (int mf = 0; mf < 2; ++mf) {
            float rm0 = -1e30f, rm1 = -1e30f;
#pragma unroll
            for (int nf = 0; nf < 8; ++nf) {
                const float2 ma = *(const float2*)&maddc[nf * 8 + 2 * tg];
                s[mf][nf][0] += ma.x; s[mf][nf][1] += ma.y;
                s[mf][nf][2] += ma.x; s[mf][nf][3] += ma.y;
                rm0 = fmaxf(rm0, fmaxf(s[mf][nf][0], s[mf][nf][1]));
                rm1 = fmaxf(rm1, fmaxf(s[mf][nf][2], s[mf][nf][3]));
            }
            rm0 = fmaxf(rm0, __shfl_xor_sync(0xffffffffu, rm0, 1));
            rm0 = fmaxf(rm0, __shfl_xor_sync(0xffffffffu, rm0, 2));
            rm1 = fmaxf(rm1, __shfl_xor_sync(0xffffffffu, rm1, 1));
            rm1 = fmaxf(rm1, __shfl_xor_sync(0xffffffffu, rm1, 2));
            const float mn0 = fmaxf(m[mf][0], rm0), mn1 = fmaxf(m[mf][1], rm1);
            const float corr0 = fexp(m[mf][0] - mn0), corr1 = fexp(m[mf][1] - mn1);
            m[mf][0] = mn0; m[mf][1] = mn1;

            float rs0 = 0.0f, rs1 = 0.0f;
            const int prow0 = warp * 32 + mf * 16 + g;
#pragma unroll
            for (int nf = 0; nf < 8; ++nf) {
                const float p0 = fexp(s[mf][nf][0] - mn0);
                const float p1 = fexp(s[mf][nf][1] - mn0);
                const float p2 = fexp(s[mf][nf][2] - mn1);
                const float p3 = fexp(s[mf][nf][3] - mn1);
                rs0 += p0 + p1; rs1 += p2 + p3;
                const int col = nf * 8 + 2 * tg;
                const int w0 = (prow0 << 6) + ((((col >> 2) ^ (prow0 & 7))) << 2) + (col & 3);
                *(uint2*)&Ps[w0] = make_uint2(f2tf(p0), f2tf(p1));
                const int prow1 = prow0 + 8;
                const int w1 = (prow1 << 6) + ((((col >> 2) ^ (prow1 & 7))) << 2) + (col & 3);
                *(uint2*)&Ps[w1] = make_uint2(f2tf(p2), f2tf(p3));
            }
            rs0 += __shfl_xor_sync(0xffffffffu, rs0, 1);
            rs0 += __shfl_xor_sync(0xffffffffu, rs0, 2);
            rs1 += __shfl_xor_sync(0xffffffffu, rs1, 1);
            rs1 += __shfl_xor_sync(0xffffffffu, rs1, 2);
            l[mf][0] = l[mf][0] * corr0 + rs0;
            l[mf][1] = l[mf][1] * corr1 + rs1;
#pragma unroll
            for (int nf = 0; nf < 8; ++nf) {
                o[mf][nf][0] *= corr0; o[mf][nf][1] *= corr0;
                o[mf][nf][2] *= corr1; o[mf][nf][3] *= corr1;
            }
        }
        __syncwarp();

        // O += P V
#pragma unroll
        for (int ks = 0; ks < 8; ++ks) {
            const int ch = ks * 2;
            unsigned a[2][4];
#pragma unroll
            for (int mf = 0; mf < 2; ++mf) {
                const int r = warp * 32 + mf * 16 + ((lsub & 1) << 3) + lr;
                const unsigned ad =
                    psb + (((r << 6) + (((ch + (lsub >> 1)) ^ (r & 7)) << 2)) << 2);
                ldsm4(a[mf][0], a[mf][1], a[mf][2], a[mf][3], ad);
            }
#pragma unroll
            for (int np = 0; np < 4; ++np) {
                const int rv = np * 16 + ((lsub >> 1) << 3) + lr;
                const unsigned bd =
                    vtb + (((rv << 6) + (((ch + (lsub & 1)) ^ (rv & 7)) << 2)) << 2);
                unsigned b0, b1, b2, b3;
                ldsm4(b0, b1, b2, b3, bd);
#pragma unroll
                for (int mf = 0; mf < 2; ++mf) {
                    mma8(o[mf][np * 2 + 0], a[mf][0], a[mf][1], a[mf][2], a[mf][3], b0, b1);
                    mma8(o[mf][np * 2 + 1], a[mf][0], a[mf][1], a[mf][2], a[mf][3], b2, b3);
                }
            }
        }
        __syncthreads();   // single barrier per tile
    }

    // epilogue -> g_ctx (B, L, H*Dv)
#pragma unroll
    for (int mf = 0; mf < 2; ++mf) {
        const float inv0 = 1.0f / l[mf][0], inv1 = 1.0f / l[mf][1];
#pragma unroll
        for (int nf = 0; nf < 8; ++nf) {
            const int row = q0 + warp * 32 + mf * 16 + g;
            const int col = nf * 8 + 2 * tg;
            *(float2*)(g_ctx + hoff + (size_t)row * DM + col) =
                make_float2(o[mf][nf][0] * inv0, o[mf][nf][1] * inv0);
            *(float2*)(g_ctx + hoff + (size_t)(row + 8) * DM + col) =
                make_float2(o[mf][nf][2] * inv1, o[mf][nf][3] * inv1);
        }
    }
}

// ---------------------------------------------------------------------------
// Launch
// ---------------------------------------------------------------------------
extern "C" void kernel_launch(void* const* d_in, const int* in_sizes, int n_in,
                              void* d_out, int out_size) {
    const float* x          = (const float*)d_in[0];
    const unsigned char* mk = (const unsigned char*)d_in[1];
    const float* Wq         = (const float*)d_in[2];
    const float* Wk         = (const float*)d_in[3];
    const float* Wv         = (const float*)d_in[4];
    const float* Wo         = (const float*)d_in[5];
    float* out              = (float*)d_out;

    cudaFuncSetAttribute(qkv_gemm, cudaFuncAttributeMaxDynamicSharedMemorySize,
                         GEMM_SMEM);
    cudaFuncSetAttribute(out_gemm, cudaFuncAttributeMaxDynamicSharedMemorySize,
                         GEMM_SMEM);
    cudaFuncSetAttribute(flash_tf32, cudaFuncAttributeMaxDynamicSharedMemorySize,
                         ATT_SMEM);

    dim3 gq(DM / 128, MROWS / 256, 3);   // (8, 32, 3)
    qkv_gemm<<<gq, 256, GEMM_SMEM>>>(x, Wq, Wk, Wv);

    dim3 gf(LL / 256, BB * HH);          // (8, 64)
    flash_tf32<<<gf, 256, ATT_SMEM>>>(mk);

    dim3 go(DM / 128, MROWS / 256, 1);   // (8, 32)
    out_gemm<<<go, 256, GEMM_SMEM>>>(Wo, out);
}